// round 5
// baseline (speedup 1.0000x reference)
#include <cuda_runtime.h>

// X, Y: [64, 1, 512, 512] float32
// 3x3 separable window (w = outer(g,g), g = [WA, WB, WA]), SAME conv,
// crop [5:-5,5:-5] -> [64,502,502]; loss = sum_b mean_hw(sxx*syy - 2*sxy)
// Identity: sum(loss) = sum(sxx*syy) + 2*sum(mu_x*mu_y) - 2*sum_crop C(xy),
// where sum_crop C(xy) = sum over input pixels of A(r)*A(c)*x*y with
// A = 1 interior, A(4)=A(507)=WA, A(5)=A(506)=WA+WB (rows and cols).

#define FULLMASK 0xFFFFFFFFu
#define WA  0.30780134f
#define WB  0.38439735f
#define WAB 0.69219869f   // WA + WB

__device__ float g_part[640];
__device__ unsigned int g_cnt = 0;

struct Row { float x[6], y[6]; };

__device__ __forceinline__ Row ldrow(const float* __restrict__ Xr,
                                     const float* __restrict__ Yr,
                                     int ib, int hb) {
    Row d;
    float4 xa = *(const float4*)(Xr + ib);   // cols j0-1..j0+2 (16B aligned)
    float2 xb = *(const float2*)(Xr + hb);   // cols j0+3, j0+4
    float4 ya = *(const float4*)(Yr + ib);
    float2 yb = *(const float2*)(Yr + hb);
    d.x[0]=xa.x; d.x[1]=xa.y; d.x[2]=xa.z; d.x[3]=xa.w; d.x[4]=xb.x; d.x[5]=xb.y;
    d.y[0]=ya.x; d.y[1]=ya.y; d.y[2]=ya.z; d.y[3]=ya.w; d.y[4]=yb.x; d.y[5]=yb.y;
    return d;
}

struct St {
    float Vpx[4], Vpy[4], Vpxx[4], Vpyy[4];
    float Vqx[4], Vqy[4], Vqxx[4], Vqyy[4];
    float wc[5];          // xy col weights for cols j0-1 .. j0+3
    float mk[4], mk2[4];  // output-col masks (and 2x)
    float accP, accC;
};

__device__ __forceinline__ void htap(const Row& d, float hx[4], float hy[4],
                                     float hxx[4], float hyy[4]) {
    float q[6], r[6];
#pragma unroll
    for (int k = 0; k < 6; k++) { q[k] = d.x[k] * d.x[k]; r[k] = d.y[k] * d.y[k]; }
#pragma unroll
    for (int k = 0; k < 4; k++) {
        hx[k]  = fmaf(WA, d.x[k], fmaf(WB, d.x[k+1], WA * d.x[k+2]));
        hy[k]  = fmaf(WA, d.y[k], fmaf(WB, d.y[k+1], WA * d.y[k+2]));
        hxx[k] = fmaf(WA, q[k],   fmaf(WB, q[k+1],   WA * q[k+2]));
        hyy[k] = fmaf(WA, r[k],   fmaf(WB, r[k+1],   WA * r[k+2]));
    }
}

// xy rim/interior weighted row term: accC += rwm2 * sum_c wc[c]*x_c*y_c
__device__ __forceinline__ void xyrow(const Row& d, St& st, float rwm2) {
    float rxy = st.wc[0] * (d.x[0] * d.y[0]);
    rxy = fmaf(st.wc[1], d.x[1] * d.y[1], rxy);
    rxy = fmaf(st.wc[2], d.x[2] * d.y[2], rxy);
    rxy = fmaf(st.wc[3], d.x[3] * d.y[3], rxy);
    rxy = fmaf(st.wc[4], d.x[4] * d.y[4], rxy);
    st.accC = fmaf(rwm2, rxy, st.accC);
}

// finish output row (using Vp + WA*h), accumulate loss terms, roll Vp/Vq
__device__ __forceinline__ void vstep(const Row& d, St& st, float rwm2) {
    float hx[4], hy[4], hxx[4], hyy[4];
    htap(d, hx, hy, hxx, hyy);
    xyrow(d, st, rwm2);
#pragma unroll
    for (int k = 0; k < 4; k++) {
        float vx  = fmaf(WA, hx[k],  st.Vpx[k]);
        float vy  = fmaf(WA, hy[k],  st.Vpy[k]);
        float vxx = fmaf(WA, hxx[k], st.Vpxx[k]);
        float vyy = fmaf(WA, hyy[k], st.Vpyy[k]);
        float sxx = fmaf(-vx, vx, vxx);
        float syy = fmaf(-vy, vy, vyy);
        st.accP = fmaf(st.mk[k],  sxx * syy, st.accP);
        st.accC = fmaf(st.mk2[k], vx * vy,   st.accC);
        st.Vpx[k]  = fmaf(WB, hx[k],  st.Vqx[k]);   st.Vqx[k]  = WA * hx[k];
        st.Vpy[k]  = fmaf(WB, hy[k],  st.Vqy[k]);   st.Vqy[k]  = WA * hy[k];
        st.Vpxx[k] = fmaf(WB, hxx[k], st.Vqxx[k]);  st.Vqxx[k] = WA * hxx[k];
        st.Vpyy[k] = fmaf(WB, hyy[k], st.Vqyy[k]);  st.Vqyy[k] = WA * hyy[k];
    }
}

__device__ __forceinline__ float colW(int c) {
    if (c > 507) return 0.0f;
    if (c == 5 || c == 506) return WAB;
    if (c == 507) return WA;
    return 1.0f;
}

__global__ void __launch_bounds__(128, 5)
loss_kernel(const float* __restrict__ X, const float* __restrict__ Y,
            float* __restrict__ out) {
    const int lane = threadIdx.x & 31;
    const int wid  = threadIdx.x >> 5;
    const int unit = blockIdx.x * 4 + wid;   // 2560 warp units
    const int b   = unit / 40;               // image
    const int rem = unit - 40 * b;
    const int s   = rem & 3;                 // col stripe (128 output cols)
    const int t   = rem >> 2;                // row strip (<=51 output rows)

    const int r0   = 5 + 51 * t;
    const int rend = min(r0 + 51, 507);      // last input row of strip
    const bool t0 = (t == 0), tl = (rend == 507);

    const int j0 = 5 + 128 * s + 4 * lane;   // first of 4 output cols
    const int ib = min(j0 - 1, 504);         // float4 base, 16B aligned
    const int hb = min(j0 + 3, 508);         // float2 base

    const float* xp = X + ((size_t)b << 18) + (size_t)(r0 - 1) * 512;
    const float* yp = Y + ((size_t)b << 18) + (size_t)(r0 - 1) * 512;

    St st;
    st.accP = 0.0f; st.accC = 0.0f;
    st.wc[0] = (j0 == 5) ? WA : 0.0f;        // input col 4 (only leftmost lane)
#pragma unroll
    for (int k = 0; k < 4; k++) {
        st.wc[k + 1] = colW(j0 + k);
        st.mk[k]  = (j0 + k <= 506) ? 1.0f : 0.0f;
        st.mk2[k] = 2.0f * st.mk[k];
    }

    // ---- prime: row r0-1 seeds Vq; xy weight A(r0-1) (t0 -> WA, else 1)
    Row cur = ldrow(xp, yp, ib, hb);
    {
        float hx[4], hy[4], hxx[4], hyy[4];
        htap(cur, hx, hy, hxx, hyy);
        xyrow(cur, st, t0 ? -2.0f * WA : -2.0f);
#pragma unroll
        for (int k = 0; k < 4; k++) {
            st.Vqx[k] = WA * hx[k];   st.Vqy[k]  = WA * hy[k];
            st.Vqxx[k] = WA * hxx[k]; st.Vqyy[k] = WA * hyy[k];
        }
    }
    xp += 512; yp += 512;
    // ---- prime: row r0 -> Vp for output row r0; xy weight A(r0)
    cur = ldrow(xp, yp, ib, hb);
    {
        float hx[4], hy[4], hxx[4], hyy[4];
        htap(cur, hx, hy, hxx, hyy);
        xyrow(cur, st, t0 ? -2.0f * WAB : -2.0f);
#pragma unroll
        for (int k = 0; k < 4; k++) {
            st.Vpx[k]  = fmaf(WB, hx[k],  st.Vqx[k]);   st.Vqx[k]  = WA * hx[k];
            st.Vpy[k]  = fmaf(WB, hy[k],  st.Vqy[k]);   st.Vqy[k]  = WA * hy[k];
            st.Vpxx[k] = fmaf(WB, hxx[k], st.Vqxx[k]);  st.Vqxx[k] = WA * hxx[k];
            st.Vpyy[k] = fmaf(WB, hyy[k], st.Vqyy[k]);  st.Vqyy[k] = WA * hyy[k];
        }
    }
    xp += 512; yp += 512;
    cur = ldrow(xp, yp, ib, hb);   // row r0+1

    // ---- main loop: rows r0+1 .. rend-2, xy weight 1 (compile-time)
    for (int i = r0 + 1; i <= rend - 2; ++i) {
        xp += 512; yp += 512;
        Row nxt = ldrow(xp, yp, ib, hb);   // row i+1 <= rend-1 <= 506
        vstep(cur, st, -2.0f);
        cur = nxt;
    }
    // ---- peeled tails: rows rend-1, rend (xy owned only by last strip, rim wts)
    {
        Row nxt = ldrow(xp + 512, yp + 512, ib, hb);   // row rend <= 507
        vstep(cur, st, tl ? -2.0f * WAB : 0.0f);       // row rend-1 (506 if tl)
        vstep(nxt, st, tl ? -2.0f * WA  : 0.0f);       // row rend   (507 if tl)
    }

    // warp -> block -> grid reduction (last block finalizes)
    float acs = st.accP + st.accC;
#pragma unroll
    for (int o = 16; o > 0; o >>= 1) acs += __shfl_xor_sync(FULLMASK, acs, o);

    __shared__ float sp[4];
    __shared__ bool is_last;
    __shared__ double sh[128];
    if (lane == 0) sp[wid] = acs;
    __syncthreads();
    if (threadIdx.x == 0) {
        g_part[blockIdx.x] = (sp[0] + sp[1]) + (sp[2] + sp[3]);
        __threadfence();
        unsigned r = atomicAdd(&g_cnt, 1u);
        is_last = (r == gridDim.x - 1);
    }
    __syncthreads();
    if (is_last) {
        __threadfence();
        double ds = 0.0;
#pragma unroll
        for (int i = threadIdx.x; i < 640; i += 128) ds += (double)g_part[i];
        sh[threadIdx.x] = ds;
        __syncthreads();
        for (int o = 64; o > 0; o >>= 1) {
            if (threadIdx.x < o) sh[threadIdx.x] += sh[threadIdx.x + o];
            __syncthreads();
        }
        if (threadIdx.x == 0) {
            out[0] = (float)(sh[0] * (1.0 / 252004.0));
            g_cnt = 0;   // reset for next graph replay (deterministic)
        }
    }
}

extern "C" void kernel_launch(void* const* d_in, const int* in_sizes, int n_in,
                              void* d_out, int out_size) {
    const float* X = (const float*)d_in[0];
    const float* Y = (const float*)d_in[1];
    float* out = (float*)d_out;

    // 2560 warps = 64 images x 4 col-stripes(128) x 10 row-strips(~51); 4/block
    loss_kernel<<<640, 128>>>(X, Y, out);
}